// round 1
// baseline (speedup 1.0000x reference)
#include <cuda_runtime.h>
#include <cuda_bf16.h>

// Scratch accumulators (no device allocation allowed)
__device__ double g_iou_sum;
__device__ double g_mse_sum;
__device__ unsigned int g_n_corr;
__device__ unsigned int g_n_inc;

__global__ void init_kernel() {
    g_iou_sum = 0.0;
    g_mse_sum = 0.0;
    g_n_corr = 0u;
    g_n_inc = 0u;
}

__global__ void __launch_bounds__(256) iou_dots_main(
    const float4* __restrict__ pr,
    const float4* __restrict__ gt,
    int n)
{
    float iou_sum = 0.0f;
    float mse_sum = 0.0f;
    unsigned int n_corr = 0u;
    unsigned int n_inc = 0u;

    const int stride = gridDim.x * blockDim.x;
    for (int i = blockIdx.x * blockDim.x + threadIdx.x; i < n; i += stride) {
        const float4 p = pr[i];
        const float4 g = gt[i];

        // gt corners (cx,cy,w,h -> xyxy)
        const float x_min_t = g.x - g.z * 0.5f;
        const float x_max_t = g.x + g.z * 0.5f;
        const float y_min_t = g.y - g.w * 0.5f;
        const float y_max_t = g.y + g.w * 0.5f;
        // pred corners clipped to [0,1]
        const float x_min_p = fmaxf(p.x - p.z * 0.5f, 0.0f);
        const float x_max_p = fminf(p.x + p.z * 0.5f, 1.0f);
        const float y_min_p = fmaxf(p.y - p.w * 0.5f, 0.0f);
        const float y_max_p = fminf(p.y + p.w * 0.5f, 1.0f);
        // overlap box
        const float o0 = fmaxf(x_min_t, x_min_p);
        const float o1 = fmaxf(y_min_t, y_min_p);
        const float o2 = fminf(x_max_t, x_max_p);
        const float o3 = fminf(y_max_t, y_max_p);

        const bool incorrect = (o2 < o0) || (o3 < o1);
        if (incorrect) {
            n_inc++;
            const float dx = p.x - g.x;
            const float dy = p.y - g.y;
            const float dz = p.z - g.z;
            const float dw = p.w - g.w;
            mse_sum += dx * dx + dy * dy + dz * dz + dw * dw;
        } else {
            n_corr++;
            const float inter = (o2 - o0) * (o3 - o1);
            const float area_p = p.z * p.w;
            const float area_g = g.z * g.w;
            iou_sum += inter / (area_p + area_g - inter + 1e-7f);
        }
    }

    // warp reduce
    #pragma unroll
    for (int off = 16; off > 0; off >>= 1) {
        iou_sum += __shfl_down_sync(0xFFFFFFFFu, iou_sum, off);
        mse_sum += __shfl_down_sync(0xFFFFFFFFu, mse_sum, off);
        n_corr  += __shfl_down_sync(0xFFFFFFFFu, n_corr, off);
        n_inc   += __shfl_down_sync(0xFFFFFFFFu, n_inc, off);
    }

    __shared__ float s_iou[8];
    __shared__ float s_mse[8];
    __shared__ unsigned int s_nc[8];
    __shared__ unsigned int s_ni[8];
    const int wid = threadIdx.x >> 5;
    const int lid = threadIdx.x & 31;
    if (lid == 0) {
        s_iou[wid] = iou_sum;
        s_mse[wid] = mse_sum;
        s_nc[wid] = n_corr;
        s_ni[wid] = n_inc;
    }
    __syncthreads();
    if (wid == 0) {
        iou_sum = (lid < 8) ? s_iou[lid] : 0.0f;
        mse_sum = (lid < 8) ? s_mse[lid] : 0.0f;
        n_corr  = (lid < 8) ? s_nc[lid] : 0u;
        n_inc   = (lid < 8) ? s_ni[lid] : 0u;
        #pragma unroll
        for (int off = 4; off > 0; off >>= 1) {
            iou_sum += __shfl_down_sync(0xFFFFFFFFu, iou_sum, off);
            mse_sum += __shfl_down_sync(0xFFFFFFFFu, mse_sum, off);
            n_corr  += __shfl_down_sync(0xFFFFFFFFu, n_corr, off);
            n_inc   += __shfl_down_sync(0xFFFFFFFFu, n_inc, off);
        }
        if (lid == 0) {
            atomicAdd(&g_iou_sum, (double)iou_sum);
            atomicAdd(&g_mse_sum, (double)mse_sum);
            atomicAdd(&g_n_corr, n_corr);
            atomicAdd(&g_n_inc, n_inc);
        }
    }
}

__global__ void finalize_kernel(float* __restrict__ out) {
    const unsigned int n_inc = g_n_inc;
    const unsigned int n_corr = g_n_corr;
    const double mse_denom = (double)((n_inc * 4u > 0u) ? n_inc * 4u : 1u);
    const double iou_denom = (double)((n_corr > 0u) ? n_corr : 1u);
    const float mse_mean = (float)(g_mse_sum / mse_denom);
    const float iou_mean = (float)(g_iou_sum / iou_denom);
    float res_full = iou_mean + ((n_inc > 0u) ? -mse_mean : 0.0f);
    out[0] = (n_corr > 0u) ? res_full : -mse_mean;
}

extern "C" void kernel_launch(void* const* d_in, const int* in_sizes, int n_in,
                              void* d_out, int out_size) {
    const float4* pr = (const float4*)d_in[0];
    const float4* gt = (const float4*)d_in[1];
    float* out = (float*)d_out;
    const int n = in_sizes[0] / 4;  // number of boxes

    init_kernel<<<1, 1>>>();
    const int threads = 256;
    const int blocks = 148 * 16;  // grid-stride; ~13 boxes/thread
    iou_dots_main<<<blocks, threads>>>(pr, gt, n);
    finalize_kernel<<<1, 1>>>(out);
}